// round 1
// baseline (speedup 1.0000x reference)
#include <cuda_runtime.h>
#include <mma.h>
#include <math.h>

using namespace nvcuda;

#define H 128
#define MMAX 50000
#define LMAX 400000
#define EPS 1e-9f

// ---------------- scratch (static __device__ globals; no allocation) -------------
__device__ float g_XW[5][MMAX * H];   // Wi x+b, Wf x+b, Wo x+b, Wc x+b, Ua x
__device__ float g_HW[2][MMAX * H];   // Wa h+b (Ah), Uf h (Ufh)
__device__ float g_UH[3][MMAX * H];   // Ui hhat, Uo hhat, Uc hhat
__device__ float g_hhat[MMAX * H];
__device__ float g_sfc[MMAX * H];
__device__ float g_xexp[LMAX];
__device__ float g_segsum[MMAX];

// ---------------- helpers -------------------------------------------------------
__device__ __forceinline__ float sigf(float x) { return 1.f / (1.f + __expf(-x)); }

__device__ __forceinline__ void red_add_f32x4(float* addr, float a, float b, float c, float d) {
    asm volatile("red.global.add.v4.f32 [%0], {%1,%2,%3,%4};"
                 :: "l"(addr), "f"(a), "f"(b), "f"(c), "f"(d) : "memory");
}

// ---------------- zero / init ---------------------------------------------------
__global__ void zero_kernel(int M) {
    int n = M * H;
    for (int i = blockIdx.x * blockDim.x + threadIdx.x; i < n; i += gridDim.x * blockDim.x) {
        g_hhat[i] = 0.f;
        g_sfc[i]  = 0.f;
        if (i < M) g_segsum[i] = 0.f;
    }
}

// ---------------- multi-weight tf32 GEMM: O[w] = A @ W[w]^T + b[w] --------------
// A: [M,128] row-major. W[w]: [128,128] row-major (out-features x in-features).
// Block: 256 threads (8 warps), tile = 128 rows x 128 cols, K=128.
struct GArgs {
    const float* W[5];
    const float* b[5];
    float*       O[5];
    int nW;
    int M;
};

__global__ void __launch_bounds__(256) gemm_tf32_kernel(const float* __restrict__ A, GArgs g) {
    extern __shared__ float sm[];
    float* sA = sm;               // 128*128 floats (64 KB)
    float* sW = sm + H * H;       // 128*128 floats (64 KB), also epilogue staging

    const int tid  = threadIdx.x;
    const int warp = tid >> 5;
    const int row0 = blockIdx.x * 128;

    // load A tile (rows beyond M -> 0)
    {
        const float4* A4 = reinterpret_cast<const float4*>(A);
        float4* sA4 = reinterpret_cast<float4*>(sA);
        for (int i = tid; i < 128 * 32; i += 256) {
            int r = i >> 5, c = i & 31;
            int gr = row0 + r;
            sA4[i] = (gr < g.M) ? A4[gr * 32 + c] : make_float4(0.f, 0.f, 0.f, 0.f);
        }
    }

    for (int w = 0; w < g.nW; ++w) {
        __syncthreads();   // sA ready / staging from previous weight consumed
        // stage weight into smem
        {
            const float4* W4 = reinterpret_cast<const float4*>(g.W[w]);
            float4* sW4 = reinterpret_cast<float4*>(sW);
            for (int i = tid; i < 128 * 32; i += 256) sW4[i] = __ldg(W4 + i);
        }
        __syncthreads();

        wmma::fragment<wmma::accumulator, 16, 16, 8, float> acc[8];
        #pragma unroll
        for (int nt = 0; nt < 8; ++nt) wmma::fill_fragment(acc[nt], 0.f);

        #pragma unroll
        for (int kt = 0; kt < 16; ++kt) {
            wmma::fragment<wmma::matrix_a, 16, 16, 8, wmma::precision::tf32, wmma::row_major> aF;
            wmma::load_matrix_sync(aF, sA + warp * 16 * H + kt * 8, H);
            #pragma unroll
            for (int i = 0; i < aF.num_elements; ++i) aF.x[i] = wmma::__float_to_tf32(aF.x[i]);
            #pragma unroll
            for (int nt = 0; nt < 8; ++nt) {
                wmma::fragment<wmma::matrix_b, 16, 16, 8, wmma::precision::tf32, wmma::col_major> bF;
                // B[k][n] = W[n][k] : col-major view of row-major W, ld = 128
                wmma::load_matrix_sync(bF, sW + nt * 16 * H + kt * 8, H);
                #pragma unroll
                for (int i = 0; i < bF.num_elements; ++i) bF.x[i] = wmma::__float_to_tf32(bF.x[i]);
                wmma::mma_sync(acc[nt], aF, bF, acc[nt]);
            }
        }

        __syncthreads();   // done reading sW as weight; reuse as staging
        #pragma unroll
        for (int nt = 0; nt < 8; ++nt)
            wmma::store_matrix_sync(sW + warp * 16 * H + nt * 16, acc[nt], H, wmma::mem_row_major);
        __syncthreads();

        // write out with bias (vectorized)
        const float* bias = g.b[w];
        float*       O    = g.O[w];
        const float4* sW4 = reinterpret_cast<const float4*>(sW);
        for (int i = tid; i < 128 * 32; i += 256) {
            int r = i >> 5, c4 = i & 31;
            int gr = row0 + r;
            if (gr < g.M) {
                float4 v = sW4[i];
                if (bias) {
                    float4 bb = __ldg(reinterpret_cast<const float4*>(bias) + c4);
                    v.x += bb.x; v.y += bb.y; v.z += bb.z; v.w += bb.w;
                }
                reinterpret_cast<float4*>(O)[gr * 32 + c4] = v;
            }
        }
    }
}

// ---------------- pair pass 1: e, exp(e), segment sum ---------------------------
// warp per pair. No max-subtraction needed: |e| <= sum|v_w| ~ 11.3 -> exp safe.
__global__ void __launch_bounds__(256) pair_e_kernel(
    const int* __restrict__ ci, const int* __restrict__ chi,
    const float* __restrict__ Ah, const float* __restrict__ Bx,
    const float* __restrict__ vw, int L)
{
    int l = blockIdx.x * 8 + (threadIdx.x >> 5);
    if (l >= L) return;
    int lane = threadIdx.x & 31;
    int c = __ldg(ci + l);
    int k = __ldg(chi + l);

    float4 a = __ldg(reinterpret_cast<const float4*>(Ah) + k * 32 + lane);
    float4 b = __ldg(reinterpret_cast<const float4*>(Bx) + c * 32 + lane);
    float4 v = __ldg(reinterpret_cast<const float4*>(vw) + lane);

    float s = tanhf(a.x + b.x) * v.x + tanhf(a.y + b.y) * v.y
            + tanhf(a.z + b.z) * v.z + tanhf(a.w + b.w) * v.w;
    #pragma unroll
    for (int o = 16; o; o >>= 1) s += __shfl_xor_sync(0xffffffffu, s, o);

    if (lane == 0) {
        float x = __expf(s);
        g_xexp[l] = x;
        atomicAdd(&g_segsum[c], x);
    }
}

// ---------------- pair pass 2: h_hat scatter + sum_f_c scatter ------------------
__global__ void __launch_bounds__(256) pair_scatter_kernel(
    const int* __restrict__ ci, const int* __restrict__ chi,
    const float* __restrict__ child_h, const float* __restrict__ child_c,
    const float* __restrict__ Wfx, const float* __restrict__ Ufh, int L)
{
    int l = blockIdx.x * 8 + (threadIdx.x >> 5);
    if (l >= L) return;
    int lane = threadIdx.x & 31;
    int c = __ldg(ci + l);
    int k = __ldg(chi + l);

    float attn = __ldg(&g_xexp[l]) / (__ldg(&g_segsum[c]) + EPS);

    float4 hh = __ldg(reinterpret_cast<const float4*>(child_h) + k * 32 + lane);
    float4 cc = __ldg(reinterpret_cast<const float4*>(child_c) + k * 32 + lane);
    float4 wf = __ldg(reinterpret_cast<const float4*>(Wfx) + c * 32 + lane);
    float4 uf = __ldg(reinterpret_cast<const float4*>(Ufh) + k * 32 + lane);

    // attn-weighted child_h -> h_hat[c]
    red_add_f32x4(&g_hhat[c * H + lane * 4],
                  attn * hh.x, attn * hh.y, attn * hh.z, attn * hh.w);

    // f_pair * child_c -> sum_f_c[c]
    float f0 = sigf(wf.x + uf.x) * cc.x;
    float f1 = sigf(wf.y + uf.y) * cc.y;
    float f2 = sigf(wf.z + uf.z) * cc.z;
    float f3 = sigf(wf.w + uf.w) * cc.w;
    red_add_f32x4(&g_sfc[c * H + lane * 4], f0, f1, f2, f3);
}

// ---------------- final gates --------------------------------------------------
__global__ void __launch_bounds__(256) gates_kernel(float* __restrict__ out, int M) {
    int i = blockIdx.x * blockDim.x + threadIdx.x;   // over M*32 float4s
    int n4 = M * 32;
    if (i >= n4) return;

    float4 wix = reinterpret_cast<const float4*>(g_XW[0])[i];
    float4 wox = reinterpret_cast<const float4*>(g_XW[2])[i];
    float4 wcx = reinterpret_cast<const float4*>(g_XW[3])[i];
    float4 uih = reinterpret_cast<const float4*>(g_UH[0])[i];
    float4 uoh = reinterpret_cast<const float4*>(g_UH[1])[i];
    float4 uch = reinterpret_cast<const float4*>(g_UH[2])[i];
    float4 sfc = reinterpret_cast<const float4*>(g_sfc)[i];

    float4 hv, cv;
    {
        float ig = sigf(wix.x + uih.x), og = sigf(wox.x + uoh.x), ct = tanhf(wcx.x + uch.x);
        cv.x = ig * ct + sfc.x;  hv.x = og * tanhf(cv.x);
    }
    {
        float ig = sigf(wix.y + uih.y), og = sigf(wox.y + uoh.y), ct = tanhf(wcx.y + uch.y);
        cv.y = ig * ct + sfc.y;  hv.y = og * tanhf(cv.y);
    }
    {
        float ig = sigf(wix.z + uih.z), og = sigf(wox.z + uoh.z), ct = tanhf(wcx.z + uch.z);
        cv.z = ig * ct + sfc.z;  hv.z = og * tanhf(cv.z);
    }
    {
        float ig = sigf(wix.w + uih.w), og = sigf(wox.w + uoh.w), ct = tanhf(wcx.w + uch.w);
        cv.w = ig * ct + sfc.w;  hv.w = og * tanhf(cv.w);
    }

    reinterpret_cast<float4*>(out)[i]      = hv;            // h
    reinterpret_cast<float4*>(out)[n4 + i] = cv;            // c
}

// ---------------- launch -------------------------------------------------------
extern "C" void kernel_launch(void* const* d_in, const int* in_sizes, int n_in,
                              void* d_out, int out_size)
{
    const float* x_emb   = (const float*)d_in[0];
    const float* child_h = (const float*)d_in[1];
    const float* child_c = (const float*)d_in[2];
    const int*   ci      = (const int*)d_in[3];
    const int*   chi     = (const int*)d_in[4];
    const float* Wi_w = (const float*)d_in[5];
    const float* Ui_w = (const float*)d_in[6];
    const float* Wf_w = (const float*)d_in[7];
    const float* Uf_w = (const float*)d_in[8];
    const float* Wo_w = (const float*)d_in[9];
    const float* Uo_w = (const float*)d_in[10];
    const float* Wc_w = (const float*)d_in[11];
    const float* Uc_w = (const float*)d_in[12];
    const float* Wa_w = (const float*)d_in[13];
    const float* Ua_w = (const float*)d_in[14];
    const float* Wi_b = (const float*)d_in[15];
    const float* Wf_b = (const float*)d_in[16];
    const float* Wo_b = (const float*)d_in[17];
    const float* Wc_b = (const float*)d_in[18];
    const float* Wa_b = (const float*)d_in[19];
    const float* v_w  = (const float*)d_in[20];

    const int M = in_sizes[0] / H;
    const int L = in_sizes[3];

    // resolve scratch addresses (no allocation; symbol lookup only)
    float *pXW, *pHW, *pUH, *phhat, *psfc;
    cudaGetSymbolAddress((void**)&pXW,  g_XW);
    cudaGetSymbolAddress((void**)&pHW,  g_HW);
    cudaGetSymbolAddress((void**)&pUH,  g_UH);
    cudaGetSymbolAddress((void**)&phhat, g_hhat);
    cudaGetSymbolAddress((void**)&psfc,  g_sfc);

    const size_t SL = (size_t)MMAX * H;

    static const int SMEM = 2 * H * H * (int)sizeof(float);   // 128 KB
    cudaFuncSetAttribute(gemm_tf32_kernel, cudaFuncAttributeMaxDynamicSharedMemorySize, SMEM);

    const int gridM = (M + 127) / 128;
    const int gridL = (L + 7) / 8;

    zero_kernel<<<4096, 256>>>(M);

    // x_emb projections: Wi, Wf, Wo, Wc (with biases) and Ua (no bias)
    {
        GArgs g;
        g.W[0] = Wi_w; g.W[1] = Wf_w; g.W[2] = Wo_w; g.W[3] = Wc_w; g.W[4] = Ua_w;
        g.b[0] = Wi_b; g.b[1] = Wf_b; g.b[2] = Wo_b; g.b[3] = Wc_b; g.b[4] = nullptr;
        g.O[0] = pXW + 0 * SL; g.O[1] = pXW + 1 * SL; g.O[2] = pXW + 2 * SL;
        g.O[3] = pXW + 3 * SL; g.O[4] = pXW + 4 * SL;
        g.nW = 5; g.M = M;
        gemm_tf32_kernel<<<gridM, 256, SMEM>>>(x_emb, g);
    }

    // child_h projections: Wa (+bias) -> Ah, Uf -> Ufh
    {
        GArgs g;
        g.W[0] = Wa_w; g.W[1] = Uf_w; g.W[2] = nullptr; g.W[3] = nullptr; g.W[4] = nullptr;
        g.b[0] = Wa_b; g.b[1] = nullptr; g.b[2] = nullptr; g.b[3] = nullptr; g.b[4] = nullptr;
        g.O[0] = pHW + 0 * SL; g.O[1] = pHW + 1 * SL; g.O[2] = nullptr; g.O[3] = nullptr; g.O[4] = nullptr;
        g.nW = 2; g.M = M;
        gemm_tf32_kernel<<<gridM, 256, SMEM>>>(child_h, g);
    }

    // pair pass 1: attention logits + segment sums
    pair_e_kernel<<<gridL, 256>>>(ci, chi, pHW + 0 * SL, pXW + 4 * SL, v_w, L);

    // pair pass 2: h_hat and sum_f_c scatter
    pair_scatter_kernel<<<gridL, 256>>>(ci, chi, child_h, child_c,
                                        pXW + 1 * SL, pHW + 1 * SL, L);

    // h_hat projections: Ui, Uo, Uc (no biases)
    {
        GArgs g;
        g.W[0] = Ui_w; g.W[1] = Uo_w; g.W[2] = Uc_w; g.W[3] = nullptr; g.W[4] = nullptr;
        g.b[0] = nullptr; g.b[1] = nullptr; g.b[2] = nullptr; g.b[3] = nullptr; g.b[4] = nullptr;
        g.O[0] = pUH + 0 * SL; g.O[1] = pUH + 1 * SL; g.O[2] = pUH + 2 * SL; g.O[3] = nullptr; g.O[4] = nullptr;
        g.nW = 3; g.M = M;
        gemm_tf32_kernel<<<gridM, 256, SMEM>>>(phhat, g);
    }

    // final gates -> out (h first, then c)
    gates_kernel<<<(M * 32 + 255) / 256, 256>>>((float*)d_out, M);
}

// round 2
// speedup vs baseline: 1.0618x; 1.0618x over previous
#include <cuda_runtime.h>
#include <mma.h>
#include <math.h>

using namespace nvcuda;

#define H 128
#define MMAX 50000
#define LMAX 400000
#define EPS 1e-9f
#define LDP 132   // padded smem leading dim (floats): 528B, 16B-multiple, bank-shift 4/row

// ---------------- scratch (static __device__ globals; no allocation) -------------
__device__ float g_XW[5][MMAX * H];   // Wi x+b, Wf x+b, Wo x+b, Wc x+b, Ua x
__device__ float g_HW[2][MMAX * H];   // Wa h+b (Ah), Uf h (Ufh)
__device__ float g_UH[3][MMAX * H];   // Ui hhat, Uo hhat, Uc hhat
__device__ float g_hhat[MMAX * H];
__device__ float g_sfc[MMAX * H];
__device__ float g_xexp[LMAX];
__device__ float g_segsum[MMAX];

// ---------------- helpers -------------------------------------------------------
__device__ __forceinline__ float sigf(float x) { return 1.f / (1.f + __expf(-x)); }

__device__ __forceinline__ void red_add_f32x4(float* addr, float a, float b, float c, float d) {
    asm volatile("red.global.add.v4.f32 [%0], {%1,%2,%3,%4};"
                 :: "l"(addr), "f"(a), "f"(b), "f"(c), "f"(d) : "memory");
}

__device__ __forceinline__ float4 tf32x4(float4 v) {
    v.x = wmma::__float_to_tf32(v.x);
    v.y = wmma::__float_to_tf32(v.y);
    v.z = wmma::__float_to_tf32(v.z);
    v.w = wmma::__float_to_tf32(v.w);
    return v;
}

// ---------------- zero / init ---------------------------------------------------
__global__ void zero_kernel(int M) {
    int n = M * H;
    for (int i = blockIdx.x * blockDim.x + threadIdx.x; i < n; i += gridDim.x * blockDim.x) {
        g_hhat[i] = 0.f;
        g_sfc[i]  = 0.f;
        if (i < M) g_segsum[i] = 0.f;
    }
}

// ---------------- multi-weight tf32 GEMM: O[w] = A @ W[w]^T + b[w] --------------
// A: [M,128] row-major. W[w]: [128,128] row-major (out x in).
// Block: 256 threads (8 warps), tile = 128 rows x 128 cols, K=128.
// A fragments cached in registers across the weight loop; smem padded to kill
// ldmatrix bank conflicts; tf32 conversion done once at staging time.
struct GArgs {
    const float* W[5];
    const float* b[5];
    float*       O[5];
    int nW;
    int M;
};

__global__ void __launch_bounds__(256) gemm_tf32_kernel(const float* __restrict__ A, GArgs g) {
    extern __shared__ float sm[];
    float* sA = sm;                 // 128*LDP floats
    float* sW = sm + 128 * LDP;     // 128*LDP floats (weight / epilogue staging)

    const int tid  = threadIdx.x;
    const int warp = tid >> 5;
    const int row0 = blockIdx.x * 128;

    // stage A tile (pre-converted to tf32, padded)
    {
        const float4* A4 = reinterpret_cast<const float4*>(A);
        for (int i = tid; i < 128 * 32; i += 256) {
            int r = i >> 5, c4 = i & 31;
            int gr = row0 + r;
            float4 v = (gr < g.M) ? tf32x4(A4[gr * 32 + c4]) : make_float4(0.f, 0.f, 0.f, 0.f);
            *reinterpret_cast<float4*>(sA + r * LDP + c4 * 4) = v;
        }
    }
    __syncthreads();

    // cache all A fragments for this warp's 16-row strip (reused across weights)
    wmma::fragment<wmma::matrix_a, 16, 16, 8, wmma::precision::tf32, wmma::row_major> aF[16];
    #pragma unroll
    for (int kt = 0; kt < 16; ++kt)
        wmma::load_matrix_sync(aF[kt], sA + warp * 16 * LDP + kt * 8, LDP);

    for (int w = 0; w < g.nW; ++w) {
        __syncthreads();   // prior epilogue readers done with sW
        // stage weight (pre-converted to tf32, padded)
        {
            const float4* W4 = reinterpret_cast<const float4*>(g.W[w]);
            for (int i = tid; i < 128 * 32; i += 256) {
                int r = i >> 5, c4 = i & 31;
                *reinterpret_cast<float4*>(sW + r * LDP + c4 * 4) = tf32x4(__ldg(W4 + i));
            }
        }
        __syncthreads();

        wmma::fragment<wmma::accumulator, 16, 16, 8, float> acc[8];
        #pragma unroll
        for (int nt = 0; nt < 8; ++nt) wmma::fill_fragment(acc[nt], 0.f);

        #pragma unroll
        for (int nt = 0; nt < 8; ++nt) {
            #pragma unroll
            for (int kt = 0; kt < 16; ++kt) {
                wmma::fragment<wmma::matrix_b, 16, 16, 8, wmma::precision::tf32, wmma::col_major> bF;
                // B[k][n] = W[n][k]: col-major view of row-major W, ld = LDP
                wmma::load_matrix_sync(bF, sW + nt * 16 * LDP + kt * 8, LDP);
                wmma::mma_sync(acc[nt], aF[kt], bF, acc[nt]);
            }
        }

        __syncthreads();   // all warps done reading sW -> reuse as epilogue staging
        #pragma unroll
        for (int nt = 0; nt < 8; ++nt)
            wmma::store_matrix_sync(sW + warp * 16 * LDP + nt * 16, acc[nt], LDP, wmma::mem_row_major);
        __syncthreads();

        // write out with bias (vectorized)
        const float* bias = g.b[w];
        float*       O    = g.O[w];
        for (int i = tid; i < 128 * 32; i += 256) {
            int r = i >> 5, c4 = i & 31;
            int gr = row0 + r;
            if (gr < g.M) {
                float4 v = *reinterpret_cast<const float4*>(sW + r * LDP + c4 * 4);
                if (bias) {
                    float4 bb = __ldg(reinterpret_cast<const float4*>(bias) + c4);
                    v.x += bb.x; v.y += bb.y; v.z += bb.z; v.w += bb.w;
                }
                reinterpret_cast<float4*>(O)[gr * 32 + c4] = v;
            }
        }
    }
}

// ---------------- pair pass 1: e, exp(e), segment sum ---------------------------
// warp per pair. No max-subtraction needed: |e| <= sum|v_w| ~ 11.3 -> exp safe.
__global__ void __launch_bounds__(256) pair_e_kernel(
    const int* __restrict__ ci, const int* __restrict__ chi,
    const float* __restrict__ Ah, const float* __restrict__ Bx,
    const float* __restrict__ vw, int L)
{
    int l = blockIdx.x * 8 + (threadIdx.x >> 5);
    if (l >= L) return;
    int lane = threadIdx.x & 31;
    int c = __ldg(ci + l);
    int k = __ldg(chi + l);

    float4 a = __ldg(reinterpret_cast<const float4*>(Ah) + k * 32 + lane);
    float4 b = __ldg(reinterpret_cast<const float4*>(Bx) + c * 32 + lane);
    float4 v = __ldg(reinterpret_cast<const float4*>(vw) + lane);

    float s = tanhf(a.x + b.x) * v.x + tanhf(a.y + b.y) * v.y
            + tanhf(a.z + b.z) * v.z + tanhf(a.w + b.w) * v.w;
    #pragma unroll
    for (int o = 16; o; o >>= 1) s += __shfl_xor_sync(0xffffffffu, s, o);

    if (lane == 0) {
        float x = __expf(s);
        g_xexp[l] = x;
        atomicAdd(&g_segsum[c], x);
    }
}

// ---------------- pair pass 2: h_hat scatter + sum_f_c scatter ------------------
__global__ void __launch_bounds__(256) pair_scatter_kernel(
    const int* __restrict__ ci, const int* __restrict__ chi,
    const float* __restrict__ child_h, const float* __restrict__ child_c,
    const float* __restrict__ Wfx, const float* __restrict__ Ufh, int L)
{
    int l = blockIdx.x * 8 + (threadIdx.x >> 5);
    if (l >= L) return;
    int lane = threadIdx.x & 31;
    int c = __ldg(ci + l);
    int k = __ldg(chi + l);

    float attn = __ldg(&g_xexp[l]) / (__ldg(&g_segsum[c]) + EPS);

    float4 hh = __ldg(reinterpret_cast<const float4*>(child_h) + k * 32 + lane);
    float4 cc = __ldg(reinterpret_cast<const float4*>(child_c) + k * 32 + lane);
    float4 wf = __ldg(reinterpret_cast<const float4*>(Wfx) + c * 32 + lane);
    float4 uf = __ldg(reinterpret_cast<const float4*>(Ufh) + k * 32 + lane);

    red_add_f32x4(&g_hhat[c * H + lane * 4],
                  attn * hh.x, attn * hh.y, attn * hh.z, attn * hh.w);

    float f0 = sigf(wf.x + uf.x) * cc.x;
    float f1 = sigf(wf.y + uf.y) * cc.y;
    float f2 = sigf(wf.z + uf.z) * cc.z;
    float f3 = sigf(wf.w + uf.w) * cc.w;
    red_add_f32x4(&g_sfc[c * H + lane * 4], f0, f1, f2, f3);
}

// ---------------- final gates --------------------------------------------------
__global__ void __launch_bounds__(256) gates_kernel(float* __restrict__ out, int M) {
    int i = blockIdx.x * blockDim.x + threadIdx.x;   // over M*32 float4s
    int n4 = M * 32;
    if (i >= n4) return;

    float4 wix = reinterpret_cast<const float4*>(g_XW[0])[i];
    float4 wox = reinterpret_cast<const float4*>(g_XW[2])[i];
    float4 wcx = reinterpret_cast<const float4*>(g_XW[3])[i];
    float4 uih = reinterpret_cast<const float4*>(g_UH[0])[i];
    float4 uoh = reinterpret_cast<const float4*>(g_UH[1])[i];
    float4 uch = reinterpret_cast<const float4*>(g_UH[2])[i];
    float4 sfc = reinterpret_cast<const float4*>(g_sfc)[i];

    float4 hv, cv;
    {
        float ig = sigf(wix.x + uih.x), og = sigf(wox.x + uoh.x), ct = tanhf(wcx.x + uch.x);
        cv.x = ig * ct + sfc.x;  hv.x = og * tanhf(cv.x);
    }
    {
        float ig = sigf(wix.y + uih.y), og = sigf(wox.y + uoh.y), ct = tanhf(wcx.y + uch.y);
        cv.y = ig * ct + sfc.y;  hv.y = og * tanhf(cv.y);
    }
    {
        float ig = sigf(wix.z + uih.z), og = sigf(wox.z + uoh.z), ct = tanhf(wcx.z + uch.z);
        cv.z = ig * ct + sfc.z;  hv.z = og * tanhf(cv.z);
    }
    {
        float ig = sigf(wix.w + uih.w), og = sigf(wox.w + uoh.w), ct = tanhf(wcx.w + uch.w);
        cv.w = ig * ct + sfc.w;  hv.w = og * tanhf(cv.w);
    }

    reinterpret_cast<float4*>(out)[i]      = hv;            // h
    reinterpret_cast<float4*>(out)[n4 + i] = cv;            // c
}

// ---------------- launch -------------------------------------------------------
extern "C" void kernel_launch(void* const* d_in, const int* in_sizes, int n_in,
                              void* d_out, int out_size)
{
    const float* x_emb   = (const float*)d_in[0];
    const float* child_h = (const float*)d_in[1];
    const float* child_c = (const float*)d_in[2];
    const int*   ci      = (const int*)d_in[3];
    const int*   chi     = (const int*)d_in[4];
    const float* Wi_w = (const float*)d_in[5];
    const float* Ui_w = (const float*)d_in[6];
    const float* Wf_w = (const float*)d_in[7];
    const float* Uf_w = (const float*)d_in[8];
    const float* Wo_w = (const float*)d_in[9];
    const float* Uo_w = (const float*)d_in[10];
    const float* Wc_w = (const float*)d_in[11];
    const float* Uc_w = (const float*)d_in[12];
    const float* Wa_w = (const float*)d_in[13];
    const float* Ua_w = (const float*)d_in[14];
    const float* Wi_b = (const float*)d_in[15];
    const float* Wf_b = (const float*)d_in[16];
    const float* Wo_b = (const float*)d_in[17];
    const float* Wc_b = (const float*)d_in[18];
    const float* Wa_b = (const float*)d_in[19];
    const float* v_w  = (const float*)d_in[20];

    const int M = in_sizes[0] / H;
    const int L = in_sizes[3];

    float *pXW, *pHW, *pUH, *phhat;
    cudaGetSymbolAddress((void**)&pXW,  g_XW);
    cudaGetSymbolAddress((void**)&pHW,  g_HW);
    cudaGetSymbolAddress((void**)&pUH,  g_UH);
    cudaGetSymbolAddress((void**)&phhat, g_hhat);

    const size_t SL = (size_t)MMAX * H;

    static const int SMEM = 2 * 128 * LDP * (int)sizeof(float);   // ~136 KB
    cudaFuncSetAttribute(gemm_tf32_kernel, cudaFuncAttributeMaxDynamicSharedMemorySize, SMEM);

    const int gridM = (M + 127) / 128;
    const int gridL = (L + 7) / 8;

    zero_kernel<<<4096, 256>>>(M);

    // x_emb projections: Wi, Wf, Wo, Wc (with biases) and Ua (no bias)
    {
        GArgs g;
        g.W[0] = Wi_w; g.W[1] = Wf_w; g.W[2] = Wo_w; g.W[3] = Wc_w; g.W[4] = Ua_w;
        g.b[0] = Wi_b; g.b[1] = Wf_b; g.b[2] = Wo_b; g.b[3] = Wc_b; g.b[4] = nullptr;
        g.O[0] = pXW + 0 * SL; g.O[1] = pXW + 1 * SL; g.O[2] = pXW + 2 * SL;
        g.O[3] = pXW + 3 * SL; g.O[4] = pXW + 4 * SL;
        g.nW = 5; g.M = M;
        gemm_tf32_kernel<<<gridM, 256, SMEM>>>(x_emb, g);
    }

    // child_h projections: Wa (+bias) -> Ah, Uf -> Ufh
    {
        GArgs g;
        g.W[0] = Wa_w; g.W[1] = Uf_w; g.W[2] = nullptr; g.W[3] = nullptr; g.W[4] = nullptr;
        g.b[0] = Wa_b; g.b[1] = nullptr; g.b[2] = nullptr; g.b[3] = nullptr; g.b[4] = nullptr;
        g.O[0] = pHW + 0 * SL; g.O[1] = pHW + 1 * SL; g.O[2] = nullptr; g.O[3] = nullptr; g.O[4] = nullptr;
        g.nW = 2; g.M = M;
        gemm_tf32_kernel<<<gridM, 256, SMEM>>>(child_h, g);
    }

    // pair pass 1: attention logits + segment sums
    pair_e_kernel<<<gridL, 256>>>(ci, chi, pHW + 0 * SL, pXW + 4 * SL, v_w, L);

    // pair pass 2: h_hat and sum_f_c scatter
    pair_scatter_kernel<<<gridL, 256>>>(ci, chi, child_h, child_c,
                                        pXW + 1 * SL, pHW + 1 * SL, L);

    // h_hat projections: Ui, Uo, Uc (no biases)
    {
        GArgs g;
        g.W[0] = Ui_w; g.W[1] = Uo_w; g.W[2] = Uc_w; g.W[3] = nullptr; g.W[4] = nullptr;
        g.b[0] = nullptr; g.b[1] = nullptr; g.b[2] = nullptr; g.b[3] = nullptr; g.b[4] = nullptr;
        g.O[0] = pUH + 0 * SL; g.O[1] = pUH + 1 * SL; g.O[2] = pUH + 2 * SL; g.O[3] = nullptr; g.O[4] = nullptr;
        g.nW = 3; g.M = M;
        gemm_tf32_kernel<<<gridM, 256, SMEM>>>(phhat, g);
    }

    // final gates -> out (h first, then c)
    gates_kernel<<<(M * 32 + 255) / 256, 256>>>((float*)d_out, M);
}

// round 4
// speedup vs baseline: 2.0734x; 1.9527x over previous
#include <cuda_runtime.h>
#include <mma.h>
#include <math.h>
#include <stdint.h>

using namespace nvcuda;

#define H 128
#define MMAX 50000
#define LMAX 400000
#define EPS 1e-9f
#define LDP 132   // padded smem leading dim (floats): 528B row stride -> 4-bank shift/row

// ---------------- scratch (static __device__ globals; no allocation) -------------
__device__ float g_XW[5][MMAX * H];   // Wi x+b, Wf x+b, Wo x+b, Wc x+b, Ua x
__device__ float g_HW[2][MMAX * H];   // Wa h+b (Ah), Uf h (Ufh)
__device__ float g_UH[3][MMAX * H];   // Ui hhat, Uo hhat, Uc hhat
__device__ float g_hhat[MMAX * H];
__device__ float g_sfc[MMAX * H];
__device__ float g_xexp[LMAX];
__device__ float g_segsum[MMAX];

// ---------------- helpers -------------------------------------------------------
__device__ __forceinline__ float sigf(float x) { return 1.f / (1.f + __expf(-x)); }

__device__ __forceinline__ float tanh_fast(float x) {
    float y; asm("tanh.approx.f32 %0, %1;" : "=f"(y) : "f"(x)); return y;
}

__device__ __forceinline__ void red_add_f32x4(float* addr, float a, float b, float c, float d) {
    asm volatile("red.global.add.v4.f32 [%0], {%1,%2,%3,%4};"
                 :: "l"(addr), "f"(a), "f"(b), "f"(c), "f"(d) : "memory");
}

__device__ __forceinline__ float4 tf32x4(float4 v) {
    v.x = wmma::__float_to_tf32(v.x);
    v.y = wmma::__float_to_tf32(v.y);
    v.z = wmma::__float_to_tf32(v.z);
    v.w = wmma::__float_to_tf32(v.w);
    return v;
}

// ---------------- zero / init ---------------------------------------------------
__global__ void zero_kernel(int M) {
    int n = M * H;
    for (int i = blockIdx.x * blockDim.x + threadIdx.x; i < n; i += gridDim.x * blockDim.x) {
        g_hhat[i] = 0.f;
        g_sfc[i]  = 0.f;
        if (i < M) g_segsum[i] = 0.f;
    }
}

// ---------------- multi-weight tf32 GEMM: O[w] = A @ W[w]^T + b[w] --------------
// A: [M,128] row-major. W: [128,128] row-major (out x in).
// Block 256 thr (8 warps, 2M x 4N), tile 128x128, warp tile 64x32. Explicit
// mma.sync.m16n8k8 tf32; conflict-free LDS via LDP padding; direct gmem epilogue.
struct GArgs {
    const float* W[5];
    const float* b[5];
    float*       O[5];
    int nW;
    int M;
};

__global__ void __launch_bounds__(256) gemm_tf32_kernel(const float* __restrict__ A, GArgs g) {
    extern __shared__ float sm[];
    float* sA = sm;                 // 128*LDP
    float* sW = sm + 128 * LDP;     // 128*LDP

    const int tid    = threadIdx.x;
    const int warp   = tid >> 5;
    const int lane   = tid & 31;
    const int gq     = lane >> 2;     // 0-7
    const int tg     = lane & 3;      // 0-3
    const int warp_m = warp & 1;      // 0-1  (64 rows each)
    const int warp_n = warp >> 1;     // 0-3  (32 cols each)
    const int row0   = blockIdx.x * 128;

    // stage A tile (tf32-rounded, padded)
    {
        const float4* A4 = reinterpret_cast<const float4*>(A);
        for (int i = tid; i < 128 * 32; i += 256) {
            int r = i >> 5, c4 = i & 31;
            int gr = row0 + r;
            float4 v = (gr < g.M) ? tf32x4(A4[gr * 32 + c4]) : make_float4(0.f, 0.f, 0.f, 0.f);
            *reinterpret_cast<float4*>(sA + r * LDP + c4 * 4) = v;
        }
    }
    __syncthreads();

    for (int w = 0; w < g.nW; ++w) {
        if (w) __syncthreads();   // all warps done reading sW from prior weight
        {
            const float4* W4 = reinterpret_cast<const float4*>(g.W[w]);
            for (int i = tid; i < 128 * 32; i += 256) {
                int r = i >> 5, c4 = i & 31;
                *reinterpret_cast<float4*>(sW + r * LDP + c4 * 4) = tf32x4(__ldg(W4 + i));
            }
        }
        __syncthreads();

        float acc[4][4][4];
        #pragma unroll
        for (int mt = 0; mt < 4; ++mt)
            #pragma unroll
            for (int nt = 0; nt < 4; ++nt)
                #pragma unroll
                for (int e = 0; e < 4; ++e) acc[mt][nt][e] = 0.f;

        #pragma unroll
        for (int k0 = 0; k0 < 128; k0 += 8) {
            uint32_t af[4][4];
            #pragma unroll
            for (int mt = 0; mt < 4; ++mt) {
                const float* ab = sA + (warp_m * 64 + mt * 16 + gq) * LDP + k0 + tg;
                af[mt][0] = __float_as_uint(ab[0]);
                af[mt][1] = __float_as_uint(ab[8 * LDP]);
                af[mt][2] = __float_as_uint(ab[4]);
                af[mt][3] = __float_as_uint(ab[8 * LDP + 4]);
            }
            #pragma unroll
            for (int nt = 0; nt < 4; ++nt) {
                const float* bb = sW + (warp_n * 32 + nt * 8 + gq) * LDP + k0 + tg;
                uint32_t b0 = __float_as_uint(bb[0]);
                uint32_t b1 = __float_as_uint(bb[4]);
                #pragma unroll
                for (int mt = 0; mt < 4; ++mt) {
                    asm volatile(
                        "mma.sync.aligned.m16n8k8.row.col.f32.tf32.tf32.f32 "
                        "{%0,%1,%2,%3}, {%4,%5,%6,%7}, {%8,%9}, {%0,%1,%2,%3};"
                        : "+f"(acc[mt][nt][0]), "+f"(acc[mt][nt][1]),
                          "+f"(acc[mt][nt][2]), "+f"(acc[mt][nt][3])
                        : "r"(af[mt][0]), "r"(af[mt][1]), "r"(af[mt][2]), "r"(af[mt][3]),
                          "r"(b0), "r"(b1));
                }
            }
        }

        // direct epilogue: c0=C[gq][2tg], c1=C[gq][2tg+1], c2=C[gq+8][2tg], c3=C[gq+8][2tg+1]
        const float* bias = g.b[w];
        float*       O    = g.O[w];
        #pragma unroll
        for (int nt = 0; nt < 4; ++nt) {
            int col = warp_n * 32 + nt * 8 + tg * 2;
            float2 bb = make_float2(0.f, 0.f);
            if (bias) bb = *reinterpret_cast<const float2*>(bias + col);
            #pragma unroll
            for (int mt = 0; mt < 4; ++mt) {
                int gr = row0 + warp_m * 64 + mt * 16 + gq;
                if (gr < g.M)
                    *reinterpret_cast<float2*>(O + gr * H + col) =
                        make_float2(acc[mt][nt][0] + bb.x, acc[mt][nt][1] + bb.y);
                if (gr + 8 < g.M)
                    *reinterpret_cast<float2*>(O + (gr + 8) * H + col) =
                        make_float2(acc[mt][nt][2] + bb.x, acc[mt][nt][3] + bb.y);
            }
        }
    }
}

// ---------------- pair pass 1: e, exp(e), segment sum ---------------------------
// warp per pair. No max-subtraction: |e| <= sum|v_w| ~ 11.3 -> exp safe in fp32.
__global__ void __launch_bounds__(256) pair_e_kernel(
    const int* __restrict__ ci, const int* __restrict__ chi,
    const float* __restrict__ Ah, const float* __restrict__ Bx,
    const float* __restrict__ vw, int L)
{
    int l = blockIdx.x * 8 + (threadIdx.x >> 5);
    if (l >= L) return;
    int lane = threadIdx.x & 31;
    int c = __ldg(ci + l);
    int k = __ldg(chi + l);

    float4 a = __ldg(reinterpret_cast<const float4*>(Ah) + k * 32 + lane);
    float4 b = __ldg(reinterpret_cast<const float4*>(Bx) + c * 32 + lane);
    float4 v = __ldg(reinterpret_cast<const float4*>(vw) + lane);

    float s = tanh_fast(a.x + b.x) * v.x + tanh_fast(a.y + b.y) * v.y
            + tanh_fast(a.z + b.z) * v.z + tanh_fast(a.w + b.w) * v.w;
    #pragma unroll
    for (int o = 16; o; o >>= 1) s += __shfl_xor_sync(0xffffffffu, s, o);

    if (lane == 0) {
        float x = __expf(s);
        g_xexp[l] = x;
        atomicAdd(&g_segsum[c], x);
    }
}

// ---------------- pair pass 2: h_hat scatter + sum_f_c scatter ------------------
__global__ void __launch_bounds__(256) pair_scatter_kernel(
    const int* __restrict__ ci, const int* __restrict__ chi,
    const float* __restrict__ child_h, const float* __restrict__ child_c,
    const float* __restrict__ Wfx, const float* __restrict__ Ufh, int L)
{
    int l = blockIdx.x * 8 + (threadIdx.x >> 5);
    if (l >= L) return;
    int lane = threadIdx.x & 31;
    int c = __ldg(ci + l);
    int k = __ldg(chi + l);

    float attn = __ldg(&g_xexp[l]) / (__ldg(&g_segsum[c]) + EPS);

    float4 hh = __ldg(reinterpret_cast<const float4*>(child_h) + k * 32 + lane);
    float4 cc = __ldg(reinterpret_cast<const float4*>(child_c) + k * 32 + lane);
    float4 wf = __ldg(reinterpret_cast<const float4*>(Wfx) + c * 32 + lane);
    float4 uf = __ldg(reinterpret_cast<const float4*>(Ufh) + k * 32 + lane);

    red_add_f32x4(&g_hhat[c * H + lane * 4],
                  attn * hh.x, attn * hh.y, attn * hh.z, attn * hh.w);

    float f0 = sigf(wf.x + uf.x) * cc.x;
    float f1 = sigf(wf.y + uf.y) * cc.y;
    float f2 = sigf(wf.z + uf.z) * cc.z;
    float f3 = sigf(wf.w + uf.w) * cc.w;
    red_add_f32x4(&g_sfc[c * H + lane * 4], f0, f1, f2, f3);
}

// ---------------- final gates --------------------------------------------------
__global__ void __launch_bounds__(256) gates_kernel(float* __restrict__ out, int M) {
    int i = blockIdx.x * blockDim.x + threadIdx.x;   // over M*32 float4s
    int n4 = M * 32;
    if (i >= n4) return;

    float4 wix = reinterpret_cast<const float4*>(g_XW[0])[i];
    float4 wox = reinterpret_cast<const float4*>(g_XW[2])[i];
    float4 wcx = reinterpret_cast<const float4*>(g_XW[3])[i];
    float4 uih = reinterpret_cast<const float4*>(g_UH[0])[i];
    float4 uoh = reinterpret_cast<const float4*>(g_UH[1])[i];
    float4 uch = reinterpret_cast<const float4*>(g_UH[2])[i];
    float4 sfc = reinterpret_cast<const float4*>(g_sfc)[i];

    float4 hv, cv;
    {
        float ig = sigf(wix.x + uih.x), og = sigf(wox.x + uoh.x), ct = tanh_fast(wcx.x + uch.x);
        cv.x = ig * ct + sfc.x;  hv.x = og * tanh_fast(cv.x);
    }
    {
        float ig = sigf(wix.y + uih.y), og = sigf(wox.y + uoh.y), ct = tanh_fast(wcx.y + uch.y);
        cv.y = ig * ct + sfc.y;  hv.y = og * tanh_fast(cv.y);
    }
    {
        float ig = sigf(wix.z + uih.z), og = sigf(wox.z + uoh.z), ct = tanh_fast(wcx.z + uch.z);
        cv.z = ig * ct + sfc.z;  hv.z = og * tanh_fast(cv.z);
    }
    {
        float ig = sigf(wix.w + uih.w), og = sigf(wox.w + uoh.w), ct = tanh_fast(wcx.w + uch.w);
        cv.w = ig * ct + sfc.w;  hv.w = og * tanh_fast(cv.w);
    }

    reinterpret_cast<float4*>(out)[i]      = hv;            // h
    reinterpret_cast<float4*>(out)[n4 + i] = cv;            // c
}

// ---------------- launch -------------------------------------------------------
extern "C" void kernel_launch(void* const* d_in, const int* in_sizes, int n_in,
                              void* d_out, int out_size)
{
    const float* x_emb   = (const float*)d_in[0];
    const float* child_h = (const float*)d_in[1];
    const float* child_c = (const float*)d_in[2];
    const int*   ci      = (const int*)d_in[3];
    const int*   chi     = (const int*)d_in[4];
    const float* Wi_w = (const float*)d_in[5];
    const float* Ui_w = (const float*)d_in[6];
    const float* Wf_w = (const float*)d_in[7];
    const float* Uf_w = (const float*)d_in[8];
    const float* Wo_w = (const float*)d_in[9];
    const float* Uo_w = (const float*)d_in[10];
    const float* Wc_w = (const float*)d_in[11];
    const float* Uc_w = (const float*)d_in[12];
    const float* Wa_w = (const float*)d_in[13];
    const float* Ua_w = (const float*)d_in[14];
    const float* Wi_b = (const float*)d_in[15];
    const float* Wf_b = (const float*)d_in[16];
    const float* Wo_b = (const float*)d_in[17];
    const float* Wc_b = (const float*)d_in[18];
    const float* Wa_b = (const float*)d_in[19];
    const float* v_w  = (const float*)d_in[20];

    const int M = in_sizes[0] / H;
    const int L = in_sizes[3];

    float *pXW, *pHW, *pUH, *phhat;
    cudaGetSymbolAddress((void**)&pXW,  g_XW);
    cudaGetSymbolAddress((void**)&pHW,  g_HW);
    cudaGetSymbolAddress((void**)&pUH,  g_UH);
    cudaGetSymbolAddress((void**)&phhat, g_hhat);

    const size_t SL = (size_t)MMAX * H;

    static const int SMEM = 2 * 128 * LDP * (int)sizeof(float);   // ~132 KB
    cudaFuncSetAttribute(gemm_tf32_kernel, cudaFuncAttributeMaxDynamicSharedMemorySize, SMEM);

    const int gridM = (M + 127) / 128;
    const int gridL = (L + 7) / 8;

    zero_kernel<<<4096, 256>>>(M);

    // x_emb projections: Wi, Wf, Wo, Wc (with biases) and Ua (no bias)
    {
        GArgs g;
        g.W[0] = Wi_w; g.W[1] = Wf_w; g.W[2] = Wo_w; g.W[3] = Wc_w; g.W[4] = Ua_w;
        g.b[0] = Wi_b; g.b[1] = Wf_b; g.b[2] = Wo_b; g.b[3] = Wc_b; g.b[4] = nullptr;
        g.O[0] = pXW + 0 * SL; g.O[1] = pXW + 1 * SL; g.O[2] = pXW + 2 * SL;
        g.O[3] = pXW + 3 * SL; g.O[4] = pXW + 4 * SL;
        g.nW = 5; g.M = M;
        gemm_tf32_kernel<<<gridM, 256, SMEM>>>(x_emb, g);
    }

    // child_h projections: Wa (+bias) -> Ah, Uf -> Ufh
    {
        GArgs g;
        g.W[0] = Wa_w; g.W[1] = Uf_w; g.W[2] = nullptr; g.W[3] = nullptr; g.W[4] = nullptr;
        g.b[0] = Wa_b; g.b[1] = nullptr; g.b[2] = nullptr; g.b[3] = nullptr; g.b[4] = nullptr;
        g.O[0] = pHW + 0 * SL; g.O[1] = pHW + 1 * SL; g.O[2] = nullptr; g.O[3] = nullptr; g.O[4] = nullptr;
        g.nW = 2; g.M = M;
        gemm_tf32_kernel<<<gridM, 256, SMEM>>>(child_h, g);
    }

    // pair pass 1: attention logits + segment sums
    pair_e_kernel<<<gridL, 256>>>(ci, chi, pHW + 0 * SL, pXW + 4 * SL, v_w, L);

    // pair pass 2: h_hat and sum_f_c scatter
    pair_scatter_kernel<<<gridL, 256>>>(ci, chi, child_h, child_c,
                                        pXW + 1 * SL, pHW + 1 * SL, L);

    // h_hat projections: Ui, Uo, Uc (no biases)
    {
        GArgs g;
        g.W[0] = Ui_w; g.W[1] = Uo_w; g.W[2] = Uc_w; g.W[3] = nullptr; g.W[4] = nullptr;
        g.b[0] = nullptr; g.b[1] = nullptr; g.b[2] = nullptr; g.b[3] = nullptr; g.b[4] = nullptr;
        g.O[0] = pUH + 0 * SL; g.O[1] = pUH + 1 * SL; g.O[2] = pUH + 2 * SL; g.O[3] = nullptr; g.O[4] = nullptr;
        g.nW = 3; g.M = M;
        gemm_tf32_kernel<<<gridM, 256, SMEM>>>(phhat, g);
    }

    // final gates -> out (h first, then c)
    gates_kernel<<<(M * 32 + 255) / 256, 256>>>((float*)d_out, M);
}